// round 1
// baseline (speedup 1.0000x reference)
#include <cuda_runtime.h>

// MultinomialModule: inverse-CDF multinomial sampling
//   cdf = cumsum(x); cdf /= cdf[-1]; idx = searchsorted(cdf, u, right); out = mean(idx)
//
// Pipeline (all graph-capturable, no allocations; scratch in __device__ globals):
//   k_init       : zero the global index accumulator
//   k_tile_sums  : per-1024-element tile sums                  (ntiles blocks)
//   k_scan_tiles : single-block scan of tile sums -> offsets, fences, 1/total
//   k_cdf        : per-tile inclusive scan, write normalized CDF
//   k_search     : two-level binary search (smem fences + L2 tile search),
//                  block-reduce idx sum, one atomicAdd per block
//   k_final      : out[0] = sum / M

#define TILE   1024
#define NT_MAX 1024                 // supports N up to 1,048,576
#define NMAX   (NT_MAX * TILE)

__device__ float g_cdf[NMAX];
__device__ float g_tile_sums[NT_MAX];
__device__ float g_tile_off[NT_MAX];
__device__ float g_fence[NT_MAX];
__device__ float g_inv_total;
__device__ unsigned long long g_sum;

__global__ void k_init() { g_sum = 0ull; }

// ---- Kernel 1: per-tile sums (256 threads, 4 elements/thread, order matches k_cdf) ----
__global__ void k_tile_sums(const float* __restrict__ x, int N) {
    int tile = blockIdx.x;
    int base = tile * TILE;
    int t = threadIdx.x;
    int i0 = base + t * 4;
    float s = 0.f;
    #pragma unroll
    for (int k = 0; k < 4; k++) {
        int i = i0 + k;
        if (i < N) s += x[i];
    }
    #pragma unroll
    for (int off = 16; off; off >>= 1) s += __shfl_down_sync(0xffffffffu, s, off);
    __shared__ float wsum[8];
    if ((t & 31) == 0) wsum[t >> 5] = s;
    __syncthreads();
    if (t < 8) {
        float v = wsum[t];
        #pragma unroll
        for (int off = 4; off; off >>= 1) v += __shfl_down_sync(0xffu, v, off);
        if (t == 0) g_tile_sums[tile] = v;
    }
}

// ---- Kernel 2: scan the tile sums (one block of 1024 threads) ----
__global__ void k_scan_tiles(int ntiles) {
    __shared__ float sh[NT_MAX];
    int t = threadIdx.x;
    float v = (t < ntiles) ? g_tile_sums[t] : 0.f;
    sh[t] = v;
    __syncthreads();
    #pragma unroll
    for (int off = 1; off < NT_MAX; off <<= 1) {
        float add = (t >= off) ? sh[t - off] : 0.f;
        __syncthreads();
        sh[t] += add;
        __syncthreads();
    }
    float incl  = sh[t];
    float total = sh[ntiles - 1];
    float inv   = 1.0f / total;
    if (t == 0) g_inv_total = inv;
    if (t < ntiles) {
        g_tile_off[t] = incl - v;          // exclusive tile offset
        g_fence[t]    = incl * inv;        // normalized last element of tile t
    } else {
        g_fence[t] = __int_as_float(0x7f800000);  // +inf padding
    }
}

// ---- Kernel 3: within-tile inclusive scan, write normalized CDF ----
__global__ void k_cdf(const float* __restrict__ x, int N) {
    int tile = blockIdx.x;
    int base = tile * TILE;
    int t = threadIdx.x;           // 256
    int lane = t & 31;
    int w = t >> 5;
    int i0 = base + t * 4;
    float v[4];
    #pragma unroll
    for (int k = 0; k < 4; k++) {
        int i = i0 + k;
        v[k] = (i < N) ? x[i] : 0.f;
    }
    float s = ((v[0] + v[1]) + v[2]) + v[3];
    // warp inclusive scan of per-thread sums
    float sc = s;
    #pragma unroll
    for (int off = 1; off < 32; off <<= 1) {
        float n = __shfl_up_sync(0xffffffffu, sc, off);
        if (lane >= off) sc += n;
    }
    __shared__ float wtot[8];
    __shared__ float woff[8];
    if (lane == 31) wtot[w] = sc;
    __syncthreads();
    if (t < 8) {
        float wv = wtot[t];
        float ws = wv;
        #pragma unroll
        for (int off = 1; off < 8; off <<= 1) {
            float n = __shfl_up_sync(0xffu, ws, off);
            if (t >= off) ws += n;
        }
        woff[t] = ws - wv;   // exclusive warp offset
    }
    __syncthreads();
    float excl = (sc - s) + woff[w];
    float acc  = g_tile_off[tile] + excl;
    float inv  = g_inv_total;
    #pragma unroll
    for (int k = 0; k < 4; k++) {
        int i = i0 + k;
        if (i < N) {
            acc += v[k];
            g_cdf[i] = acc * inv;
        }
    }
}

// ---- Kernel 4: two-level search + mean accumulation ----
__global__ void k_search(const float* __restrict__ u, int M, int N, int ntiles) {
    __shared__ float fence[NT_MAX];
    for (int i = threadIdx.x; i < NT_MAX; i += blockDim.x)
        fence[i] = g_fence[i];
    __syncthreads();

    int j = blockIdx.x * blockDim.x + threadIdx.x;
    unsigned long long myidx = 0;
    if (j < M) {
        float uu = u[j];
        // level 1: count fences <= uu (branchless binary search over 1024 smem entries)
        int t = 0;
        #pragma unroll
        for (int step = NT_MAX / 2; step > 0; step >>= 1)
            if (fence[t + step - 1] <= uu) t += step;

        long long idx;
        if (t >= ntiles) {
            idx = N;
        } else {
            // level 2: upper bound within tile t in global CDF (L2-resident)
            int lo = t * TILE;
            int hi = min(N, lo + TILE);
            int pos = lo;
            #pragma unroll
            for (int step = TILE / 2; step > 0; step >>= 1) {
                int probe = pos + step - 1;
                if (probe < hi && __ldg(&g_cdf[probe]) <= uu) pos += step;
            }
            idx = pos;
        }
        if (idx > (long long)(N - 1)) idx = N - 1;
        myidx = (unsigned long long)idx;
    }

    // block-level sum of indices
    #pragma unroll
    for (int off = 16; off; off >>= 1)
        myidx += __shfl_down_sync(0xffffffffu, myidx, off);
    __shared__ unsigned long long ws[8];
    int lane = threadIdx.x & 31, w = threadIdx.x >> 5;
    if (lane == 0) ws[w] = myidx;
    __syncthreads();
    if (threadIdx.x < 8) {
        unsigned long long v = ws[threadIdx.x];
        #pragma unroll
        for (int off = 4; off; off >>= 1)
            v += __shfl_down_sync(0xffu, v, off);
        if (threadIdx.x == 0) atomicAdd(&g_sum, v);
    }
}

// ---- Kernel 5: finalize mean ----
__global__ void k_final(float* out, int M) {
    out[0] = (float)((double)g_sum / (double)M);
}

extern "C" void kernel_launch(void* const* d_in, const int* in_sizes, int n_in,
                              void* d_out, int out_size) {
    const float* x = (const float*)d_in[0];
    const float* u = (const float*)d_in[1];
    float* out = (float*)d_out;
    int N = in_sizes[0];
    int M = in_sizes[1];
    int ntiles = (N + TILE - 1) / TILE;

    k_init<<<1, 1>>>();
    k_tile_sums<<<ntiles, 256>>>(x, N);
    k_scan_tiles<<<1, NT_MAX>>>(ntiles);
    k_cdf<<<ntiles, 256>>>(x, N);
    int sblocks = (M + 255) / 256;
    k_search<<<sblocks, 256>>>(u, M, N, ntiles);
    k_final<<<1, 1>>>(out, M);
}

// round 2
// speedup vs baseline: 1.8823x; 1.8823x over previous
#include <cuda_runtime.h>

// MultinomialModule: inverse-CDF multinomial sampling with a guide table.
//   cdf = cumsum(x)/total; T[k] = searchsorted(cdf, k/K); per-sample O(1) repair.
//
// Pipeline:
//   k_tile_sums  : per-1024-element tile sums (float4)
//   k_scan_tiles : single-block scan of tile sums -> offsets, 1/total; zero g_sum
//   k_cdf        : per-tile inclusive scan, write normalized CDF (float4)
//   k_scatter    : build guide table T[k] by range scatter (exact partition)
//   k_search     : idx = repair(T[floor(u*K)]); block-reduce; atomicAdd
//   k_final      : out[0] = sum / M

#define TILE   1024
#define NT_MAX 1024
#define NMAX   (NT_MAX * TILE)
#define KBITS  20
#define KTAB   (1 << KBITS)          // 2^20 guide bins

__device__ float g_cdf[NMAX];
__device__ int   g_T[KTAB];
__device__ float g_tile_sums[NT_MAX];
__device__ float g_tile_off[NT_MAX];
__device__ float g_inv_total;
__device__ unsigned long long g_sum;

// ---- Kernel 1: per-tile sums (256 threads, float4) ----
__global__ void k_tile_sums(const float* __restrict__ x, int N) {
    int tile = blockIdx.x;
    int base = tile * TILE;
    int t = threadIdx.x;
    int i0 = base + t * 4;
    float s = 0.f;
    if (i0 + 3 < N) {
        float4 v = *reinterpret_cast<const float4*>(x + i0);
        s = ((v.x + v.y) + v.z) + v.w;
    } else {
        #pragma unroll
        for (int k = 0; k < 4; k++) {
            int i = i0 + k;
            if (i < N) s += x[i];
        }
    }
    #pragma unroll
    for (int off = 16; off; off >>= 1) s += __shfl_down_sync(0xffffffffu, s, off);
    __shared__ float wsum[8];
    if ((t & 31) == 0) wsum[t >> 5] = s;
    __syncthreads();
    if (t < 8) {
        float v = wsum[t];
        #pragma unroll
        for (int off = 4; off; off >>= 1) v += __shfl_down_sync(0xffu, v, off);
        if (t == 0) g_tile_sums[tile] = v;
    }
}

// ---- Kernel 2: scan tile sums (one block of 1024 threads); also zero g_sum ----
__global__ void k_scan_tiles(int ntiles) {
    __shared__ float sh[NT_MAX];
    int t = threadIdx.x;
    if (t == 0) g_sum = 0ull;
    float v = (t < ntiles) ? g_tile_sums[t] : 0.f;
    sh[t] = v;
    __syncthreads();
    #pragma unroll
    for (int off = 1; off < NT_MAX; off <<= 1) {
        float add = (t >= off) ? sh[t - off] : 0.f;
        __syncthreads();
        sh[t] += add;
        __syncthreads();
    }
    float incl  = sh[t];
    float total = sh[ntiles - 1];
    if (t == 0) g_inv_total = 1.0f / total;
    if (t < ntiles) g_tile_off[t] = incl - v;   // exclusive tile offset
}

// ---- Kernel 3: within-tile inclusive scan, write normalized CDF (float4) ----
__global__ void k_cdf(const float* __restrict__ x, int N) {
    int tile = blockIdx.x;
    int base = tile * TILE;
    int t = threadIdx.x;           // 256
    int lane = t & 31;
    int w = t >> 5;
    int i0 = base + t * 4;
    float v[4];
    bool full = (i0 + 3 < N);
    if (full) {
        float4 f = *reinterpret_cast<const float4*>(x + i0);
        v[0] = f.x; v[1] = f.y; v[2] = f.z; v[3] = f.w;
    } else {
        #pragma unroll
        for (int k = 0; k < 4; k++) {
            int i = i0 + k;
            v[k] = (i < N) ? x[i] : 0.f;
        }
    }
    float s = ((v[0] + v[1]) + v[2]) + v[3];
    float sc = s;
    #pragma unroll
    for (int off = 1; off < 32; off <<= 1) {
        float n = __shfl_up_sync(0xffffffffu, sc, off);
        if (lane >= off) sc += n;
    }
    __shared__ float wtot[8];
    __shared__ float woff[8];
    if (lane == 31) wtot[w] = sc;
    __syncthreads();
    if (t < 8) {
        float wv = wtot[t];
        float ws = wv;
        #pragma unroll
        for (int off = 1; off < 8; off <<= 1) {
            float n = __shfl_up_sync(0xffu, ws, off);
            if (t >= off) ws += n;
        }
        woff[t] = ws - wv;
    }
    __syncthreads();
    float excl = (sc - s) + woff[w];
    float acc  = g_tile_off[tile] + excl;
    float inv  = g_inv_total;
    if (full) {
        float4 o;
        acc += v[0]; o.x = acc * inv;
        acc += v[1]; o.y = acc * inv;
        acc += v[2]; o.z = acc * inv;
        acc += v[3]; o.w = acc * inv;
        *reinterpret_cast<float4*>(g_cdf + i0) = o;
    } else {
        #pragma unroll
        for (int k = 0; k < 4; k++) {
            int i = i0 + k;
            if (i < N) {
                acc += v[k];
                g_cdf[i] = acc * inv;
            }
        }
    }
}

// ---- Kernel 4: build guide table by range scatter ----
// Thread i owns bins k with cdf[i-1] <= k/K < cdf[i]:
//   [ceil(cdf[i-1]*K), ceil(cdf[i]*K))  -- adjacent threads share the boundary
//   expression, so the ranges exactly partition [0, K). Last thread forced to K.
__global__ void k_scatter(int N) {
    int i = blockIdx.x * blockDim.x + threadIdx.x;
    if (i >= N) return;
    float prev = (i > 0) ? g_cdf[i - 1] : 0.f;
    float cur  = g_cdf[i];
    int a = (int)ceilf(prev * (float)KTAB);
    int b = (i == N - 1) ? KTAB : (int)ceilf(cur * (float)KTAB);
    if (a < 0) a = 0;
    if (b > KTAB) b = KTAB;
    for (int k = a; k < b; k++) g_T[k] = i;
}

// ---- Kernel 5: guided search + mean accumulation ----
__global__ void k_search(const float* __restrict__ u, int M, int N) {
    int j = blockIdx.x * blockDim.x + threadIdx.x;
    unsigned long long myidx = 0;
    if (j < M) {
        float uu = u[j];
        unsigned k = (unsigned)(uu * (float)KTAB);
        if (k >= KTAB) k = KTAB - 1;
        int pos = __ldg(&g_T[k]);
        if (pos < 0) pos = 0;
        if (pos > N) pos = N;
        // exact repair to searchsorted(cdf, uu, 'right'):
        while (pos > 0 && __ldg(&g_cdf[pos - 1]) > uu) pos--;
        while (pos < N && __ldg(&g_cdf[pos]) <= uu) pos++;
        if (pos > N - 1) pos = N - 1;
        myidx = (unsigned long long)pos;
    }
    #pragma unroll
    for (int off = 16; off; off >>= 1)
        myidx += __shfl_down_sync(0xffffffffu, myidx, off);
    __shared__ unsigned long long ws[8];
    int lane = threadIdx.x & 31, w = threadIdx.x >> 5;
    if (lane == 0) ws[w] = myidx;
    __syncthreads();
    if (threadIdx.x < 8) {
        unsigned long long v = ws[threadIdx.x];
        #pragma unroll
        for (int off = 4; off; off >>= 1)
            v += __shfl_down_sync(0xffu, v, off);
        if (threadIdx.x == 0) atomicAdd(&g_sum, v);
    }
}

// ---- Kernel 6: finalize mean ----
__global__ void k_final(float* out, int M) {
    out[0] = (float)((double)g_sum / (double)M);
}

extern "C" void kernel_launch(void* const* d_in, const int* in_sizes, int n_in,
                              void* d_out, int out_size) {
    const float* x = (const float*)d_in[0];
    const float* u = (const float*)d_in[1];
    float* out = (float*)d_out;
    int N = in_sizes[0];
    int M = in_sizes[1];
    int ntiles = (N + TILE - 1) / TILE;

    k_tile_sums<<<ntiles, 256>>>(x, N);
    k_scan_tiles<<<1, NT_MAX>>>(ntiles);
    k_cdf<<<ntiles, 256>>>(x, N);
    k_scatter<<<(N + 255) / 256, 256>>>(N);
    k_search<<<(M + 255) / 256, 256>>>(u, M, N);
    k_final<<<1, 1>>>(out, M);
}

// round 3
// speedup vs baseline: 2.4707x; 1.3126x over previous
#include <cuda_runtime.h>
#include <math_constants.h>

// MultinomialModule: inverse-CDF multinomial with self-validating guide table.
//   g_E[k] = {idx, cdf[idx-1], cdf[idx], cdf[idx+1]} for bins k covering
//   cdf[idx-1] <= k/K < cdf[idx].  Query: one 16B load resolves most samples;
//   exact memory walk otherwise. Entries carry bitwise copies of g_cdf values,
//   so scatter races at float boundaries cannot change the final (exact) index.
//
// Pipeline:
//   k_tile_sums  : per-1024-element tile sums (float4)
//   k_scan_tiles : shuffle-scan of tile sums -> offsets, 1/total; zero g_sum
//   k_cdf        : per-tile scan -> normalized CDF + fused guide-table scatter
//   k_search     : guided O(1) search (float4 u), block-reduce, atomicAdd
//   k_final      : out[0] = sum / M

#define TILE   1024
#define NT_MAX 1024
#define NMAX   (NT_MAX * TILE)
#define KBITS  20
#define KTAB   (1 << KBITS)

__device__ float  g_cdf[NMAX];
__device__ float4 g_E[KTAB];          // 16MB guide table
__device__ float  g_tile_sums[NT_MAX];
__device__ float  g_tile_off[NT_MAX];
__device__ float  g_inv_total;
__device__ unsigned long long g_sum;

// ---- Kernel 1: per-tile sums (256 threads, float4) ----
__global__ void k_tile_sums(const float* __restrict__ x, int N) {
    int tile = blockIdx.x;
    int t = threadIdx.x;
    int i0 = tile * TILE + t * 4;
    float s = 0.f;
    if (i0 + 3 < N) {
        float4 v = *reinterpret_cast<const float4*>(x + i0);
        s = ((v.x + v.y) + v.z) + v.w;
    } else {
        #pragma unroll
        for (int k = 0; k < 4; k++) if (i0 + k < N) s += x[i0 + k];
    }
    #pragma unroll
    for (int off = 16; off; off >>= 1) s += __shfl_down_sync(0xffffffffu, s, off);
    __shared__ float wsum[8];
    if ((t & 31) == 0) wsum[t >> 5] = s;
    __syncthreads();
    if (t < 8) {
        float v = wsum[t];
        #pragma unroll
        for (int off = 4; off; off >>= 1) v += __shfl_down_sync(0xffu, v, off);
        if (t == 0) g_tile_sums[tile] = v;
    }
}

// ---- Kernel 2: shuffle-scan of tile sums (1024 threads, 2 barriers) ----
__global__ void k_scan_tiles(int ntiles) {
    int t = threadIdx.x, lane = t & 31, w = t >> 5;
    if (t == 0) g_sum = 0ull;
    float v = (t < ntiles) ? g_tile_sums[t] : 0.f;
    float sc = v;
    #pragma unroll
    for (int off = 1; off < 32; off <<= 1) {
        float n = __shfl_up_sync(0xffffffffu, sc, off);
        if (lane >= off) sc += n;
    }
    __shared__ float wtot[32];
    __shared__ float sh_total;
    if (lane == 31) wtot[w] = sc;
    __syncthreads();
    if (w == 0) {
        float ws = wtot[lane];
        #pragma unroll
        for (int off = 1; off < 32; off <<= 1) {
            float n = __shfl_up_sync(0xffffffffu, ws, off);
            if (lane >= off) ws += n;
        }
        wtot[lane] = ws;                 // inclusive warp totals
    }
    __syncthreads();
    float incl = sc + ((w > 0) ? wtot[w - 1] : 0.f);
    if (t == ntiles - 1) sh_total = incl;
    __syncthreads();
    if (t == 0) g_inv_total = 1.0f / sh_total;
    if (t < ntiles) g_tile_off[t] = incl - v;      // exclusive tile offset
}

// ---- Kernel 3: CDF + fused guide-table scatter (256 threads, 4 elems/thread) ----
__global__ void k_cdf(const float* __restrict__ x, int N) {
    int tile = blockIdx.x;
    int base = tile * TILE;
    int t = threadIdx.x;
    int lane = t & 31, w = t >> 5;
    int i0 = base + t * 4;
    float v[4];
    bool full = (i0 + 3 < N);
    if (full) {
        float4 f = *reinterpret_cast<const float4*>(x + i0);
        v[0] = f.x; v[1] = f.y; v[2] = f.z; v[3] = f.w;
    } else {
        #pragma unroll
        for (int k = 0; k < 4; k++) v[k] = (i0 + k < N) ? x[i0 + k] : 0.f;
    }
    float s = ((v[0] + v[1]) + v[2]) + v[3];
    float sc = s;
    #pragma unroll
    for (int off = 1; off < 32; off <<= 1) {
        float n = __shfl_up_sync(0xffffffffu, sc, off);
        if (lane >= off) sc += n;
    }
    __shared__ float wtot[8];
    __shared__ float woff[8];
    if (lane == 31) wtot[w] = sc;
    __syncthreads();
    if (t < 8) {
        float wv = wtot[t];
        float ws = wv;
        #pragma unroll
        for (int off = 1; off < 8; off <<= 1) {
            float n = __shfl_up_sync(0xffu, ws, off);
            if (t >= off) ws += n;
        }
        woff[t] = ws - wv;
    }
    __syncthreads();
    float acc = g_tile_off[tile] + (sc - s) + woff[w];
    float inv = g_inv_total;

    float pn0 = acc * inv;                 // normalized exclusive start
    float c[4];
    #pragma unroll
    for (int k = 0; k < 4; k++) { acc += v[k]; c[k] = acc * inv; }

    if (full) {
        *reinterpret_cast<float4*>(g_cdf + i0) = make_float4(c[0], c[1], c[2], c[3]);
    } else {
        #pragma unroll
        for (int k = 0; k < 4; k++) if (i0 + k < N) g_cdf[i0 + k] = c[k];
    }

    // neighbor exchange for bitwise-exact entry payloads
    __shared__ float sh_c0[256], sh_c3[256];
    sh_c0[t] = c[0]; sh_c3[t] = c[3];
    __syncthreads();
    float nb_prev = (t > 0)   ? sh_c3[t - 1] : CUDART_INF_F;  // sentinel -> exact backward walk
    float nb_next = (t < 255) ? sh_c0[t + 1] : -1.0f;         // sentinel -> exact forward walk

    float prevc = pn0;
    #pragma unroll
    for (int k = 0; k < 4; k++) {
        int i = i0 + k;
        if (i >= N) break;
        float cm1 = (k == 0) ? nb_prev : c[k - 1];
        float c1  = (k < 3)  ? c[k + 1] : nb_next;
        int a = (int)ceilf(prevc * (float)KTAB);
        if (a < 0) a = 0;
        int b = (i == N - 1) ? KTAB : (int)ceilf(c[k] * (float)KTAB);
        if (b > KTAB) b = KTAB;
        int bend = (k == 3 && b < KTAB) ? b + 1 : b;   // cover ulp gaps at thread seams
        if (a < bend) {
            float4 e = make_float4(__int_as_float(i), cm1, c[k], c1);
            for (int kk = a; kk < bend; kk++) g_E[kk] = e;
        }
        prevc = c[k];
    }
}

// ---- Kernel 4: guided search, 4 samples/thread ----
__device__ __forceinline__ int resolve(float uu, int N) {
    unsigned k = (unsigned)(uu * (float)KTAB);
    if (k >= KTAB) k = KTAB - 1;
    float4 e = __ldg(&g_E[k]);
    int pos = __float_as_int(e.x);
    float cm1 = e.y, c0 = e.z, c1 = e.w;
    if (uu < cm1) {                       // exact backward repair (rare)
        while (pos > 0 && __ldg(&g_cdf[pos - 1]) > uu) pos--;
    } else if (uu < c0) {
        // pos correct: cdf[pos-1] <= u < cdf[pos]
    } else if (uu < c1) {
        pos += 1;
    } else {                              // exact forward repair
        pos += 1;
        while (pos < N && __ldg(&g_cdf[pos]) <= uu) pos++;
    }
    if (pos > N - 1) pos = N - 1;
    return pos;
}

__global__ void k_search(const float* __restrict__ u, int M, int N) {
    int j0 = (blockIdx.x * blockDim.x + threadIdx.x) * 4;
    unsigned long long local = 0;
    if (j0 + 3 < M) {
        float4 uu = *reinterpret_cast<const float4*>(u + j0);
        local += (unsigned long long)resolve(uu.x, N);
        local += (unsigned long long)resolve(uu.y, N);
        local += (unsigned long long)resolve(uu.z, N);
        local += (unsigned long long)resolve(uu.w, N);
    } else {
        for (int k = 0; k < 4; k++)
            if (j0 + k < M) local += (unsigned long long)resolve(u[j0 + k], N);
    }
    #pragma unroll
    for (int off = 16; off; off >>= 1)
        local += __shfl_down_sync(0xffffffffu, local, off);
    __shared__ unsigned long long ws[8];
    int lane = threadIdx.x & 31, w = threadIdx.x >> 5;
    if (lane == 0) ws[w] = local;
    __syncthreads();
    if (threadIdx.x < 8) {
        unsigned long long v = ws[threadIdx.x];
        #pragma unroll
        for (int off = 4; off; off >>= 1)
            v += __shfl_down_sync(0xffu, v, off);
        if (threadIdx.x == 0) atomicAdd(&g_sum, v);
    }
}

// ---- Kernel 5: finalize mean ----
__global__ void k_final(float* out, int M) {
    out[0] = (float)((double)g_sum / (double)M);
}

extern "C" void kernel_launch(void* const* d_in, const int* in_sizes, int n_in,
                              void* d_out, int out_size) {
    const float* x = (const float*)d_in[0];
    const float* u = (const float*)d_in[1];
    float* out = (float*)d_out;
    int N = in_sizes[0];
    int M = in_sizes[1];
    int ntiles = (N + TILE - 1) / TILE;

    k_tile_sums<<<ntiles, 256>>>(x, N);
    k_scan_tiles<<<1, NT_MAX>>>(ntiles);
    k_cdf<<<ntiles, 256>>>(x, N);
    int sthreads = (M + 3) / 4;
    k_search<<<(sthreads + 255) / 256, 256>>>(u, M, N);
    k_final<<<1, 1>>>(out, M);
}

// round 4
// speedup vs baseline: 2.6048x; 1.0543x over previous
#include <cuda_runtime.h>

// MultinomialModule via summation swap (no per-sample search):
//   sum_j searchsorted(cdf,u_j,right) = sum_i ( M - #{u_j < cdf[i]} )
//   #{u < v} = U[floor(v*K)] + H[floor(v*K)] * frac(v*K)   (u uniform in bin)
// where H = histogram of u over K=2^20 bins, U = exclusive prefix sum of H.
// Clip idx to N-1  <=>  skip the i = N-1 term.
// Correction quantized to 1/65536 -> integer atomics -> deterministic.
//
// Pipeline (7 launches):
//   k_zero   : H = 0, g_acc = 0
//   k_hist   : histogram of u (red.global.add)
//   k_sums   : tile sums of H (int) and of x (float) in one grid
//   k_scans  : block 0 = int scan of H-tile sums; block 1 = float scan of x-tile sums
//   k_U      : write exclusive prefix U of H
//   k_gather : per-tile x scan -> cdf in registers -> gather U/H -> accumulate
//   k_final  : out = g_acc / (65536 * M)

#define TILE   1024
#define NT_MAX 1024
#define KBITS  20
#define KTAB   (1 << KBITS)

__device__ int   g_H[KTAB];
__device__ int   g_U[KTAB];
__device__ int   g_hsum[NT_MAX];
__device__ int   g_hoff[NT_MAX];
__device__ float g_xsum[NT_MAX];
__device__ float g_xoff[NT_MAX];
__device__ float g_inv_total;
__device__ unsigned long long g_acc;

// ---- A: zero histogram + accumulator (K/4 int4 stores) ----
__global__ void k_zero() {
    int i = blockIdx.x * blockDim.x + threadIdx.x;   // 1024*256 = K/4
    reinterpret_cast<int4*>(g_H)[i] = make_int4(0, 0, 0, 0);
    if (i == 0) g_acc = 0ull;
}

// ---- B: histogram of u ----
__device__ __forceinline__ void hbump(float v) {
    unsigned b = (unsigned)(v * (float)KTAB);        // exact: *2^20
    if (b >= KTAB) b = KTAB - 1;
    atomicAdd(&g_H[b], 1);
}
__global__ void k_hist(const float* __restrict__ u, int M) {
    int j0 = (blockIdx.x * blockDim.x + threadIdx.x) * 4;
    if (j0 + 3 < M) {
        float4 v = *reinterpret_cast<const float4*>(u + j0);
        hbump(v.x); hbump(v.y); hbump(v.z); hbump(v.w);
    } else {
        for (int k = 0; k < 4; k++) if (j0 + k < M) hbump(u[j0 + k]);
    }
}

// ---- C: tile sums for H (blocks 0..1023, int) and x (blocks 1024.., float) ----
__global__ void k_sums(const float* __restrict__ x, int N, int ntiles) {
    int b = blockIdx.x;
    int t = threadIdx.x;
    if (b < NT_MAX) {
        int i0 = b * TILE + t * 4;
        int4 h = *reinterpret_cast<const int4*>(g_H + i0);
        int s = h.x + h.y + h.z + h.w;
        #pragma unroll
        for (int off = 16; off; off >>= 1) s += __shfl_down_sync(0xffffffffu, s, off);
        __shared__ int wsum[8];
        if ((t & 31) == 0) wsum[t >> 5] = s;
        __syncthreads();
        if (t < 8) {
            int v = wsum[t];
            #pragma unroll
            for (int off = 4; off; off >>= 1) v += __shfl_down_sync(0xffu, v, off);
            if (t == 0) g_hsum[b] = v;
        }
    } else {
        int tile = b - NT_MAX;
        if (tile >= ntiles) return;
        int i0 = tile * TILE + t * 4;
        float s = 0.f;
        if (i0 + 3 < N) {
            float4 v = *reinterpret_cast<const float4*>(x + i0);
            s = ((v.x + v.y) + v.z) + v.w;
        } else {
            #pragma unroll
            for (int k = 0; k < 4; k++) if (i0 + k < N) s += x[i0 + k];
        }
        #pragma unroll
        for (int off = 16; off; off >>= 1) s += __shfl_down_sync(0xffffffffu, s, off);
        __shared__ float wsumf[8];
        if ((t & 31) == 0) wsumf[t >> 5] = s;
        __syncthreads();
        if (t < 8) {
            float v = wsumf[t];
            #pragma unroll
            for (int off = 4; off; off >>= 1) v += __shfl_down_sync(0xffu, v, off);
            if (t == 0) g_xsum[tile] = v;
        }
    }
}

// ---- D: scan both tile-sum arrays (block 0 int, block 1 float) ----
__global__ void k_scans(int ntiles) {
    int t = threadIdx.x, lane = t & 31, w = t >> 5;
    if (blockIdx.x == 0) {
        int v = g_hsum[t];
        int sc = v;
        #pragma unroll
        for (int off = 1; off < 32; off <<= 1) {
            int n = __shfl_up_sync(0xffffffffu, sc, off);
            if (lane >= off) sc += n;
        }
        __shared__ int wtot[32];
        if (lane == 31) wtot[w] = sc;
        __syncthreads();
        if (w == 0) {
            int ws = wtot[lane];
            #pragma unroll
            for (int off = 1; off < 32; off <<= 1) {
                int n = __shfl_up_sync(0xffffffffu, ws, off);
                if (lane >= off) ws += n;
            }
            wtot[lane] = ws;
        }
        __syncthreads();
        int incl = sc + ((w > 0) ? wtot[w - 1] : 0);
        g_hoff[t] = incl - v;                        // exclusive H-tile offset
    } else {
        float v = (t < ntiles) ? g_xsum[t] : 0.f;
        float sc = v;
        #pragma unroll
        for (int off = 1; off < 32; off <<= 1) {
            float n = __shfl_up_sync(0xffffffffu, sc, off);
            if (lane >= off) sc += n;
        }
        __shared__ float wtotf[32];
        __shared__ float sh_total;
        if (lane == 31) wtotf[w] = sc;
        __syncthreads();
        if (w == 0) {
            float ws = wtotf[lane];
            #pragma unroll
            for (int off = 1; off < 32; off <<= 1) {
                float n = __shfl_up_sync(0xffffffffu, ws, off);
                if (lane >= off) ws += n;
            }
            wtotf[lane] = ws;
        }
        __syncthreads();
        float incl = sc + ((w > 0) ? wtotf[w - 1] : 0.f);
        if (t == ntiles - 1) sh_total = incl;
        __syncthreads();
        if (t == 0) g_inv_total = 1.0f / sh_total;
        if (t < ntiles) g_xoff[t] = incl - v;        // exclusive x-tile offset
    }
}

// ---- E: materialize exclusive prefix U of H ----
__global__ void k_U() {
    int tile = blockIdx.x;
    int t = threadIdx.x, lane = t & 31, w = t >> 5;
    int i0 = tile * TILE + t * 4;
    int4 h = *reinterpret_cast<const int4*>(g_H + i0);
    int s = h.x + h.y + h.z + h.w;
    int sc = s;
    #pragma unroll
    for (int off = 1; off < 32; off <<= 1) {
        int n = __shfl_up_sync(0xffffffffu, sc, off);
        if (lane >= off) sc += n;
    }
    __shared__ int wtot[8];
    __shared__ int woff[8];
    if (lane == 31) wtot[w] = sc;
    __syncthreads();
    if (t < 8) {
        int wv = wtot[t];
        int ws = wv;
        #pragma unroll
        for (int off = 1; off < 8; off <<= 1) {
            int n = __shfl_up_sync(0xffu, ws, off);
            if (t >= off) ws += n;
        }
        woff[t] = ws - wv;
    }
    __syncthreads();
    int base = g_hoff[tile] + (sc - s) + woff[w];    // exclusive before h.x
    int4 o;
    o.x = base;
    o.y = base + h.x;
    o.z = o.y + h.y;
    o.w = o.z + h.z;
    *reinterpret_cast<int4*>(g_U + i0) = o;
}

// ---- F: x scan in registers -> gather U/H -> accumulate contributions ----
__global__ void k_gather(const float* __restrict__ x, int N, int M) {
    int tile = blockIdx.x;
    int t = threadIdx.x, lane = t & 31, w = t >> 5;
    int i0 = tile * TILE + t * 4;
    float v[4];
    bool full = (i0 + 3 < N);
    if (full) {
        float4 f = *reinterpret_cast<const float4*>(x + i0);
        v[0] = f.x; v[1] = f.y; v[2] = f.z; v[3] = f.w;
    } else {
        #pragma unroll
        for (int k = 0; k < 4; k++) v[k] = (i0 + k < N) ? x[i0 + k] : 0.f;
    }
    float s = ((v[0] + v[1]) + v[2]) + v[3];
    float sc = s;
    #pragma unroll
    for (int off = 1; off < 32; off <<= 1) {
        float n = __shfl_up_sync(0xffffffffu, sc, off);
        if (lane >= off) sc += n;
    }
    __shared__ float wtot[8];
    __shared__ float woff[8];
    if (lane == 31) wtot[w] = sc;
    __syncthreads();
    if (t < 8) {
        float wv = wtot[t];
        float ws = wv;
        #pragma unroll
        for (int off = 1; off < 8; off <<= 1) {
            float n = __shfl_up_sync(0xffu, ws, off);
            if (t >= off) ws += n;
        }
        woff[t] = ws - wv;
    }
    __syncthreads();
    float acc = g_xoff[tile] + (sc - s) + woff[w];
    float inv = g_inv_total;

    long long local = 0;
    #pragma unroll
    for (int e = 0; e < 4; e++) {
        int i = i0 + e;
        acc += v[e];
        if (i < N && i != N - 1) {                    // skip last term == clip to N-1
            float ck = (acc * inv) * (float)KTAB;     // bin coordinate (exact *2^20)
            int k = (int)ck;
            if (k > KTAB - 1) k = KTAB - 1;
            if (k < 0) k = 0;
            float frac = ck - (float)k;
            if (frac < 0.f) frac = 0.f;
            if (frac > 1.f) frac = 1.f;
            int Uv = __ldg(&g_U[k]);
            int Hv = __ldg(&g_H[k]);
            long long ip = ((long long)(M - Uv)) << 16;
            int q = (int)(frac * (float)Hv * 65536.0f);
            local += ip - (long long)q;               // >= 0 always
        }
    }
    #pragma unroll
    for (int off = 16; off; off >>= 1)
        local += __shfl_down_sync(0xffffffffu, local, off);
    __shared__ long long ws8[8];
    if (lane == 0) ws8[w] = local;
    __syncthreads();
    if (t < 8) {
        long long vv = ws8[t];
        #pragma unroll
        for (int off = 4; off; off >>= 1)
            vv += __shfl_down_sync(0xffu, vv, off);
        if (t == 0) atomicAdd(&g_acc, (unsigned long long)vv);
    }
}

// ---- G: finalize ----
__global__ void k_final(float* out, int M) {
    out[0] = (float)((double)g_acc / (65536.0 * (double)M));
}

extern "C" void kernel_launch(void* const* d_in, const int* in_sizes, int n_in,
                              void* d_out, int out_size) {
    const float* x = (const float*)d_in[0];
    const float* u = (const float*)d_in[1];
    float* out = (float*)d_out;
    int N = in_sizes[0];
    int M = in_sizes[1];
    int ntiles = (N + TILE - 1) / TILE;

    k_zero<<<KTAB / 4 / 256, 256>>>();
    k_hist<<<((M + 3) / 4 + 255) / 256, 256>>>(u, M);
    k_sums<<<NT_MAX + ntiles, 256>>>(x, N, ntiles);
    k_scans<<<2, 1024>>>(ntiles);
    k_U<<<NT_MAX, 256>>>();
    k_gather<<<ntiles, 256>>>(x, N, M);
    k_final<<<1, 1>>>(out, M);
}